// round 3
// baseline (speedup 1.0000x reference)
#include <cuda_runtime.h>
#include <math.h>

// ---------------------------------------------------------------------------
// Problem constants
//   B=2, T=4096, D=2048, H=16, HD=128
// ---------------------------------------------------------------------------
constexpr int MT = 8192;    // B*T rows
constexpr int NK = 2048;    // N and K dims of every GEMM
constexpr int HEADS = 16;
constexpr int HD = 128;
constexpr int TSEQ = 4096;
constexpr int BATCH = 2;

#define EXP_OFFSET (-3.8123084930796303f)

// GEMM tiling
constexpr int BM = 128, BN = 128, BK = 16;
constexpr int APAD = 20;             // A plane row stride (floats)
constexpr int BPAD = 136;            // B plane row stride (floats)
constexpr int AHS = BM * APAD;       // 2560 floats per A plane
constexpr int BHS = BK * BPAD;       // 2176 floats per B plane
// per-stage layout: [A_hi][A_lo][B_hi][B_lo]
constexpr int OFF_AH = 0;
constexpr int OFF_AL = AHS;
constexpr int OFF_BH = 2 * AHS;
constexpr int OFF_BL = 2 * AHS + BHS;
constexpr int STAGE = 2 * AHS + 2 * BHS;   // 9472 floats
constexpr int NSTAGE = 3;
constexpr int SMEM_BYTES = NSTAGE * STAGE * 4;  // 113664 B

// Scan tiling
constexpr int CHUNKS = 16;
constexpr int CLEN = TSEQ / CHUNKS;  // 256

// ---------------------------------------------------------------------------
// Scratch (static device globals; allocation is forbidden)
// ---------------------------------------------------------------------------
__device__ float g_hsh[MT * NK];
__device__ float g_hsl[MT * NK];
__device__ float g_qh [MT * NK];   // q hi; later reused as attn hi
__device__ float g_ql [MT * NK];   // q lo; later reused as attn lo
__device__ float g_kh [MT * NK];
__device__ float g_kl [MT * NK];
__device__ float g_v  [MT * NK];
__device__ float g_qp [MT * NK];
__device__ float g_kp [MT * NK];
__device__ float g_wh [6 * NK * NK];  // Wq,Wk,Wv,Wo,Fq,Fk hi planes
__device__ float g_wl [6 * NK * NK];  // lo planes
__device__ float g_dot [BATCH * HEADS * TSEQ];
__device__ float g_csum[BATCH * HEADS * CHUNKS * HD];

// ---------------------------------------------------------------------------
// Helpers
// ---------------------------------------------------------------------------
__device__ __forceinline__ void cpasync16(float* s, const float* g) {
    unsigned sa = (unsigned)__cvta_generic_to_shared(s);
    asm volatile("cp.async.cg.shared.global [%0], [%1], 16;\n" :: "r"(sa), "l"(g));
}

// Split fp32 into hi+lo tf32 pair (values stored as fp32 bit patterns)
__device__ __forceinline__ void split_tf32(float f, float& hi, float& lo) {
    unsigned h;
    asm("cvt.rna.tf32.f32 %0, %1;" : "=r"(h) : "f"(f));
    float r = f - __uint_as_float(h);
    unsigned l;
    asm("cvt.rna.tf32.f32 %0, %1;" : "=r"(l) : "f"(r));
    hi = __uint_as_float(h);
    lo = __uint_as_float(l);
}

__device__ __forceinline__ void mma_tf32(float* d, const unsigned* a, const unsigned* b) {
    asm volatile(
        "mma.sync.aligned.m16n8k8.row.col.f32.tf32.tf32.f32 "
        "{%0,%1,%2,%3}, {%4,%5,%6,%7}, {%8,%9}, {%0,%1,%2,%3};\n"
        : "+f"(d[0]), "+f"(d[1]), "+f"(d[2]), "+f"(d[3])
        : "r"(a[0]), "r"(a[1]), "r"(a[2]), "r"(a[3]), "r"(b[0]), "r"(b[1]));
}

// ---------------------------------------------------------------------------
// Prep: elementwise split of a tensor into hi/lo tf32 planes (float4 strides)
// ---------------------------------------------------------------------------
__global__ void split_kernel(const float* __restrict__ in,
                             float* __restrict__ hi, float* __restrict__ lo,
                             int n4) {
    int i = blockIdx.x * blockDim.x + threadIdx.x;
    if (i >= n4) return;
    float4 x = ((const float4*)in)[i];
    float4 h4, l4;
    split_tf32(x.x, h4.x, l4.x);
    split_tf32(x.y, h4.y, l4.y);
    split_tf32(x.z, h4.z, l4.z);
    split_tf32(x.w, h4.w, l4.w);
    ((float4*)hi)[i] = h4;
    ((float4*)lo)[i] = l4;
}

// ---------------------------------------------------------------------------
// GEMM on pre-split hi/lo planes. 128x128 tile, BK=16, 3-stage cp.async,
// 8 warps at 64x32, 3xTF32 (hi*hi + hi*lo + lo*hi).
// OUT: 0 = plain fp32, 1 = exp(x+OFFSET), 2 = split hi/lo planes
// ---------------------------------------------------------------------------
__device__ __forceinline__ void load_tile(const float* __restrict__ Ahb,
                                          const float* __restrict__ Alb,
                                          const float* __restrict__ Bhb,
                                          const float* __restrict__ Blb,
                                          float* buf, int k0, int tid) {
    #pragma unroll
    for (int p = 0; p < 2; p++) {
        int i = tid + p * 256;
        // A planes: 128 rows x 16 cols = 512 float4 per plane
        int r = i >> 2;
        int q = (i & 3) << 2;
        size_t ga = (size_t)r * NK + k0 + q;
        cpasync16(&buf[OFF_AH + r * APAD + q], Ahb + ga);
        cpasync16(&buf[OFF_AL + r * APAD + q], Alb + ga);
        // B planes: 16 rows x 128 cols = 512 float4 per plane
        int br = i >> 5;
        int bq = (i & 31) << 2;
        size_t gb = (size_t)(k0 + br) * NK + bq;
        cpasync16(&buf[OFF_BH + br * BPAD + bq], Bhb + gb);
        cpasync16(&buf[OFF_BL + br * BPAD + bq], Blb + gb);
    }
    asm volatile("cp.async.commit_group;\n");
}

__device__ __forceinline__ void compute_tile(const float* buf, float acc[4][4][4],
                                             int wr, int wc, int g, int t) {
    const float* Ah = buf + OFF_AH;
    const float* Al = buf + OFF_AL;
    const float* Bh = buf + OFF_BH;
    const float* Bl = buf + OFF_BL;
    #pragma unroll
    for (int ks = 0; ks < 2; ks++) {
        const int kk = ks * 8;
        unsigned ah[4][4], al[4][4];
        #pragma unroll
        for (int mi = 0; mi < 4; mi++) {
            const int base = (wr * 64 + mi * 16 + g) * APAD + kk + t;
            ah[mi][0] = __float_as_uint(Ah[base]);
            ah[mi][1] = __float_as_uint(Ah[base + 8 * APAD]);
            ah[mi][2] = __float_as_uint(Ah[base + 4]);
            ah[mi][3] = __float_as_uint(Ah[base + 8 * APAD + 4]);
            al[mi][0] = __float_as_uint(Al[base]);
            al[mi][1] = __float_as_uint(Al[base + 8 * APAD]);
            al[mi][2] = __float_as_uint(Al[base + 4]);
            al[mi][3] = __float_as_uint(Al[base + 8 * APAD + 4]);
        }
        unsigned bh[4][2], bl[4][2];
        #pragma unroll
        for (int ni = 0; ni < 4; ni++) {
            const int bidx = (kk + t) * BPAD + wc * 32 + ni * 8 + g;
            bh[ni][0] = __float_as_uint(Bh[bidx]);
            bh[ni][1] = __float_as_uint(Bh[bidx + 4 * BPAD]);
            bl[ni][0] = __float_as_uint(Bl[bidx]);
            bl[ni][1] = __float_as_uint(Bl[bidx + 4 * BPAD]);
        }
        #pragma unroll
        for (int mi = 0; mi < 4; mi++) {
            #pragma unroll
            for (int ni = 0; ni < 4; ni++) {
                mma_tf32(acc[mi][ni], ah[mi], bh[ni]);
                mma_tf32(acc[mi][ni], ah[mi], bl[ni]);
                mma_tf32(acc[mi][ni], al[mi], bh[ni]);
            }
        }
    }
}

template <int OUT>
__global__ void __launch_bounds__(256, 1)
gemm_pre_kernel(const float* __restrict__ Ah, const float* __restrict__ Al,
                const float* __restrict__ Bh, const float* __restrict__ Bl,
                float* __restrict__ C, float* __restrict__ C2) {
    extern __shared__ float sm[];
    const int tid = threadIdx.x;
    const int lane = tid & 31;
    const int wid = tid >> 5;
    const int wr = wid >> 2;
    const int wc = wid & 3;
    const int g = lane >> 2;
    const int t = lane & 3;
    const int bm = blockIdx.y * BM;
    const int bn = blockIdx.x * BN;
    const float* Ahb = Ah + (size_t)bm * NK;
    const float* Alb = Al + (size_t)bm * NK;
    const float* Bhb = Bh + bn;
    const float* Blb = Bl + bn;

    float acc[4][4][4];
    #pragma unroll
    for (int mi = 0; mi < 4; mi++)
        #pragma unroll
        for (int ni = 0; ni < 4; ni++)
            #pragma unroll
            for (int r = 0; r < 4; r++)
                acc[mi][ni][r] = 0.0f;

    constexpr int NT = NK / BK;  // 128
    load_tile(Ahb, Alb, Bhb, Blb, sm,         0,  tid);
    load_tile(Ahb, Alb, Bhb, Blb, sm + STAGE, BK, tid);

    #pragma unroll 1
    for (int kt = 0; kt < NT; kt++) {
        asm volatile("cp.async.wait_group 1;\n");
        __syncthreads();
        if (kt + 2 < NT)
            load_tile(Ahb, Alb, Bhb, Blb, sm + ((kt + 2) % NSTAGE) * STAGE,
                      (kt + 2) * BK, tid);
        compute_tile(sm + (kt % NSTAGE) * STAGE, acc, wr, wc, g, t);
    }

    // Epilogue
    float* Cb  = C  + (size_t)bm * NK + bn;
    float* C2b = (OUT == 2) ? (C2 + (size_t)bm * NK + bn) : nullptr;
    #pragma unroll
    for (int mi = 0; mi < 4; mi++) {
        const int r0 = wr * 64 + mi * 16 + g;
        #pragma unroll
        for (int ni = 0; ni < 4; ni++) {
            const int c0 = wc * 32 + ni * 8 + 2 * t;
            float v0 = acc[mi][ni][0], v1 = acc[mi][ni][1];
            float v2 = acc[mi][ni][2], v3 = acc[mi][ni][3];
            if (OUT == 1) {
                v0 = expf(v0 + EXP_OFFSET);
                v1 = expf(v1 + EXP_OFFSET);
                v2 = expf(v2 + EXP_OFFSET);
                v3 = expf(v3 + EXP_OFFSET);
            }
            if (OUT == 2) {
                float h0, l0, h1, l1, h2, l2, h3, l3;
                split_tf32(v0, h0, l0); split_tf32(v1, h1, l1);
                split_tf32(v2, h2, l2); split_tf32(v3, h3, l3);
                *(float2*)&Cb [(size_t)r0 * NK + c0]       = make_float2(h0, h1);
                *(float2*)&Cb [(size_t)(r0 + 8) * NK + c0] = make_float2(h2, h3);
                *(float2*)&C2b[(size_t)r0 * NK + c0]       = make_float2(l0, l1);
                *(float2*)&C2b[(size_t)(r0 + 8) * NK + c0] = make_float2(l2, l3);
            } else {
                *(float2*)&Cb[(size_t)r0 * NK + c0]       = make_float2(v0, v1);
                *(float2*)&Cb[(size_t)(r0 + 8) * NK + c0] = make_float2(v2, v3);
            }
        }
    }
}

// ---------------------------------------------------------------------------
// dot[b,h,t] = sum_d qp[b,t,h*128+d] * kp[b,t,h*128+d]
// ---------------------------------------------------------------------------
__global__ void dot_kernel(const float* __restrict__ qp, const float* __restrict__ kp,
                           float* __restrict__ dotv) {
    const int row = blockIdx.x;
    const int tid = threadIdx.x;
    const float4* q4 = (const float4*)(qp + (size_t)row * NK);
    const float4* k4 = (const float4*)(kp + (size_t)row * NK);
    const int base = tid * 2;
    float4 a = q4[base], b = k4[base];
    float s = a.x * b.x + a.y * b.y + a.z * b.z + a.w * b.w;
    a = q4[base + 1]; b = k4[base + 1];
    s += a.x * b.x + a.y * b.y + a.z * b.z + a.w * b.w;
    #pragma unroll
    for (int off = 8; off >= 1; off >>= 1)
        s += __shfl_down_sync(0xffffffffu, s, off, 16);
    if ((tid & 15) == 0) {
        const int h = tid >> 4;
        const int bb = row >> 12;
        const int t = row & (TSEQ - 1);
        dotv[((size_t)bb * HEADS + h) * TSEQ + t] = s;
    }
}

// ---------------------------------------------------------------------------
// Chunked scan phase 1: per-chunk sums of dot[t]*v[t,d]
// ---------------------------------------------------------------------------
__global__ void scan1_kernel(const float* __restrict__ dotv, const float* __restrict__ v,
                             float* __restrict__ csum) {
    const int bid = blockIdx.x;
    const int c = bid & (CHUNKS - 1);
    const int bh = bid >> 4;
    const int h = bh & (HEADS - 1);
    const int b = bh >> 4;
    const int d = threadIdx.x;
    const float* dptr = dotv + (size_t)bh * TSEQ + c * CLEN;
    const float* vp = v + ((size_t)(b * TSEQ + c * CLEN)) * NK + h * HD + d;
    float s = 0.0f;
    #pragma unroll 8
    for (int i = 0; i < CLEN; i++)
        s = fmaf(dptr[i], vp[(size_t)i * NK], s);
    csum[(size_t)bid * HD + d] = s;
}

// ---------------------------------------------------------------------------
// Chunked scan phase 2: prefix offset + local cumsum + /kp, written pre-split
// into hi/lo tf32 planes (consumed directly by the final GEMM).
// ---------------------------------------------------------------------------
__global__ void scan2_kernel(const float* __restrict__ dotv, const float* __restrict__ v,
                             const float* __restrict__ kp, const float* __restrict__ csum,
                             float* __restrict__ ahi, float* __restrict__ alo) {
    const int bid = blockIdx.x;
    const int c = bid & (CHUNKS - 1);
    const int bh = bid >> 4;
    const int h = bh & (HEADS - 1);
    const int b = bh >> 4;
    const int d = threadIdx.x;

    float run = 0.0f;
    for (int c2 = 0; c2 < c; c2++)
        run += csum[((size_t)bh * CHUNKS + c2) * HD + d];

    const float* dptr = dotv + (size_t)bh * TSEQ + c * CLEN;
    const size_t off = ((size_t)(b * TSEQ + c * CLEN)) * NK + h * HD + d;
    const float* vp = v + off;
    const float* kpp = kp + off;
    float* ahp = ahi + off;
    float* alp = alo + off;
    #pragma unroll 4
    for (int i = 0; i < CLEN; i++) {
        run = fmaf(dptr[i], vp[(size_t)i * NK], run);
        float a = run / kpp[(size_t)i * NK];
        float h2, l2;
        split_tf32(a, h2, l2);
        ahp[(size_t)i * NK] = h2;
        alp[(size_t)i * NK] = l2;
    }
}

// ---------------------------------------------------------------------------
// Launch
// ---------------------------------------------------------------------------
extern "C" void kernel_launch(void* const* d_in, const int* in_sizes, int n_in,
                              void* d_out, int out_size) {
    (void)in_sizes; (void)n_in; (void)out_size;
    const float* hs = (const float*)d_in[0];
    const float* W[6] = { (const float*)d_in[1], (const float*)d_in[2],
                          (const float*)d_in[3], (const float*)d_in[4],
                          (const float*)d_in[5], (const float*)d_in[6] };
    float* out = (float*)d_out;

    float *hsh, *hsl, *qh, *ql, *kh, *kl, *v, *qp, *kp, *wh, *wl, *dotv, *csum;
    cudaGetSymbolAddress((void**)&hsh, g_hsh);
    cudaGetSymbolAddress((void**)&hsl, g_hsl);
    cudaGetSymbolAddress((void**)&qh,  g_qh);
    cudaGetSymbolAddress((void**)&ql,  g_ql);
    cudaGetSymbolAddress((void**)&kh,  g_kh);
    cudaGetSymbolAddress((void**)&kl,  g_kl);
    cudaGetSymbolAddress((void**)&v,   g_v);
    cudaGetSymbolAddress((void**)&qp,  g_qp);
    cudaGetSymbolAddress((void**)&kp,  g_kp);
    cudaGetSymbolAddress((void**)&wh,  g_wh);
    cudaGetSymbolAddress((void**)&wl,  g_wl);
    cudaGetSymbolAddress((void**)&dotv, g_dot);
    cudaGetSymbolAddress((void**)&csum, g_csum);

    // Opt-in to >48KB dynamic smem (idempotent; capture-safe host calls)
    cudaFuncSetAttribute(gemm_pre_kernel<0>, cudaFuncAttributeMaxDynamicSharedMemorySize, SMEM_BYTES);
    cudaFuncSetAttribute(gemm_pre_kernel<1>, cudaFuncAttributeMaxDynamicSharedMemorySize, SMEM_BYTES);
    cudaFuncSetAttribute(gemm_pre_kernel<2>, cudaFuncAttributeMaxDynamicSharedMemorySize, SMEM_BYTES);

    // --- Prep: split hs and all weights into tf32 hi/lo planes ---
    {
        int n4 = MT * NK / 4;           // 4M float4
        split_kernel<<<n4 / 256, 256>>>(hs, hsh, hsl, n4);
        int w4 = NK * NK / 4;           // 1M float4
        for (int i = 0; i < 6; i++)
            split_kernel<<<w4 / 256, 256>>>(W[i], wh + (size_t)i * NK * NK,
                                            wl + (size_t)i * NK * NK, w4);
    }

    const size_t WS = (size_t)NK * NK;
    dim3 ggrid(NK / BN, MT / BM);   // (16, 64)
    dim3 gblk(256);

    // q, k written pre-split (consumed by GEMMs); v plain fp32
    gemm_pre_kernel<2><<<ggrid, gblk, SMEM_BYTES>>>(hsh, hsl, wh + 0 * WS, wl + 0 * WS, qh, ql);
    gemm_pre_kernel<2><<<ggrid, gblk, SMEM_BYTES>>>(hsh, hsl, wh + 1 * WS, wl + 1 * WS, kh, kl);
    gemm_pre_kernel<0><<<ggrid, gblk, SMEM_BYTES>>>(hsh, hsl, wh + 2 * WS, wl + 2 * WS, v, nullptr);
    // q' = exp(q@Fq + off), k' = exp(k@Fk + off): plain fp32 outputs
    gemm_pre_kernel<1><<<ggrid, gblk, SMEM_BYTES>>>(qh, ql, wh + 4 * WS, wl + 4 * WS, qp, nullptr);
    gemm_pre_kernel<1><<<ggrid, gblk, SMEM_BYTES>>>(kh, kl, wh + 5 * WS, wl + 5 * WS, kp, nullptr);

    dot_kernel<<<MT, 256>>>(qp, kp, dotv);
    scan1_kernel<<<BATCH * HEADS * CHUNKS, HD>>>(dotv, v, csum);
    // attn written pre-split into qh/ql (q planes are dead after qp)
    scan2_kernel<<<BATCH * HEADS * CHUNKS, HD>>>(dotv, v, kp, csum, qh, ql);

    gemm_pre_kernel<0><<<ggrid, gblk, SMEM_BYTES>>>(qh, ql, wh + 3 * WS, wl + 3 * WS, out, nullptr);
}